// round 17
// baseline (speedup 1.0000x reference)
#include <cuda_runtime.h>
#include <cuda_bf16.h>
#include <math.h>

// ---------------------------------------------------------------------------
// GaussianSplattingDecoder.
// occ[v,c] = sum_g exp(-0.5*mahal)*opacity_g*sem_g[c] (dist^2 < R^2) + empty
// V = 100*100*8, N = 2048, C = 17.
// R16: gaussian-PAIR packed inner loop. Survivors staged as interleaved
// 2-gaussian records (means/cov as (a,b) f32x2 pairs, negated means so
// d = p + (-m) is add.rn.f32x2); dist^2 + mahalanobis evaluated for both
// gaussians with packed FMA2 (12 packed ops vs 22 scalar), 13 LDS.128 per
// pair vs 14. Iteration count halves. ~20% fewer issue slots per gaussian.
// Base: R13 (ex2-folded constants, FFMA2 class accumulate, coalesced output,
// branchless, packed means cull, chunked staging, launch_bounds(256,5)).
// ---------------------------------------------------------------------------

#define N_GAUSS 2048
#define NUM_CLASSES 17
#define PROP_STRIDE 28      // 11 + 17
#define RADIUS_SQ 16.0f
#define CULL_MARGIN 0.01f
#define STAGE_CAP 256       // gaussians per chunk (128 pairs)
#define NEG_HALF_LOG2E (-0.72134752044448170368f)   // -0.5 * log2(e)
#define NEG_LOG2E      (-1.44269504088896340736f)   // -log2(e)

// Packed means for culling: 32 KB, contiguous, L2-resident.
__device__ float4 g_means[N_GAUSS];

// Preprocessed gaussians: 7 float4s each (224 KB, L2-resident).
// Floats 0..9: -mx, -my, -mz, h00, h01, h02, h11, h12, h22, s16
//   (h** pre-scaled by -0.5*log2e / -log2e so quadform = log2-weight)
// Floats 10,11: pad. Floats 12..27 (f4[3..6]): s0..s15 (opacity-scaled).
__device__ float4 g_prep[N_GAUSS * 7];

#define FMA2(accp, pair, ww) \
    asm("fma.rn.f32x2 %0, %1, %2, %0;" : "+l"(accp) : "l"(pair), "l"(ww))
#define MUL2(dst, a, b) \
    asm("mul.rn.f32x2 %0, %1, %2;" : "=l"(dst) : "l"(a), "l"(b))
#define ADD2(dst, a, b) \
    asm("add.rn.f32x2 %0, %1, %2;" : "=l"(dst) : "l"(a), "l"(b))
#define PACK2(dst, lo, hi) \
    asm("mov.b64 %0, {%1, %2};" : "=l"(dst) : "f"(lo), "f"(hi))
#define UNPACK2(lo, hi, src) \
    asm("mov.b64 {%0, %1}, %2;" : "=f"(lo), "=f"(hi) : "l"(src))
#define EX2(dst, src) \
    asm("ex2.approx.f32 %0, %1;" : "=f"(dst) : "f"(src))

__device__ __forceinline__ float softplus_stable(float x) {
    return fmaxf(x, 0.0f) + log1pf(expf(-fabsf(x)));
}

__global__ void prep_kernel(const float* __restrict__ props) {
    int g = blockIdx.x * blockDim.x + threadIdx.x;
    if (g >= N_GAUSS) return;
    const float* p = props + g * PROP_STRIDE;

    float s0 = fmaxf(softplus_stable(p[3]), 1e-4f);
    float s1 = fmaxf(softplus_stable(p[4]), 1e-4f);
    float s2 = fmaxf(softplus_stable(p[5]), 1e-4f);
    float a0 = 1.0f / fmaxf(s0 * s0, 1e-8f);
    float a1 = 1.0f / fmaxf(s1 * s1, 1e-8f);
    float a2 = 1.0f / fmaxf(s2 * s2, 1e-8f);

    float qw = p[6], qx = p[7], qy = p[8], qz = p[9];
    float inv_n = 1.0f / fmaxf(sqrtf(qw * qw + qx * qx + qy * qy + qz * qz), 1e-8f);
    qw *= inv_n; qx *= inv_n; qy *= inv_n; qz *= inv_n;

    float R00 = 1.0f - 2.0f * (qy * qy + qz * qz);
    float R01 = 2.0f * (qx * qy - qw * qz);
    float R02 = 2.0f * (qx * qz + qw * qy);
    float R10 = 2.0f * (qx * qy + qw * qz);
    float R11 = 1.0f - 2.0f * (qx * qx + qz * qz);
    float R12 = 2.0f * (qy * qz - qw * qx);
    float R20 = 2.0f * (qx * qz - qw * qy);
    float R21 = 2.0f * (qy * qz + qw * qx);
    float R22 = 1.0f - 2.0f * (qx * qx + qy * qy);

    float c00 = a0 * R00 * R00 + a1 * R01 * R01 + a2 * R02 * R02;
    float c01 = a0 * R00 * R10 + a1 * R01 * R11 + a2 * R02 * R12;
    float c02 = a0 * R00 * R20 + a1 * R01 * R21 + a2 * R02 * R22;
    float c11 = a0 * R10 * R10 + a1 * R11 * R11 + a2 * R12 * R12;
    float c12 = a0 * R10 * R20 + a1 * R11 * R21 + a2 * R12 * R22;
    float c22 = a0 * R20 * R20 + a1 * R21 * R21 + a2 * R22 * R22;

    float op = 1.0f / (1.0f + expf(-p[10]));

    g_means[g] = make_float4(p[0], p[1], p[2], 0.0f);

    float4* o = g_prep + g * 7;
    o[0] = make_float4(-p[0], -p[1], -p[2], NEG_HALF_LOG2E * c00);
    o[1] = make_float4(NEG_LOG2E * c01, NEG_LOG2E * c02,
                       NEG_HALF_LOG2E * c11, NEG_LOG2E * c12);
    o[2] = make_float4(NEG_HALF_LOG2E * c22, op * p[27], 0.0f, 0.0f);
    o[3] = make_float4(op * p[11], op * p[12], op * p[13], op * p[14]);
    o[4] = make_float4(op * p[15], op * p[16], op * p[17], op * p[18]);
    o[5] = make_float4(op * p[19], op * p[20], op * p[21], op * p[22]);
    o[6] = make_float4(op * p[23], op * p[24], op * p[25], op * p[26]);
}

// Tile = 4x4x8 voxels. 256 threads: tid&127 -> voxel, tid>>7 -> list half.
__global__ __launch_bounds__(256, 5) void splat_kernel(
    const float* __restrict__ vox_coords, float* __restrict__ out)
{
    const int tid = threadIdx.x;
    const int tx = blockIdx.x * 4;
    const int ty = blockIdx.y * 4;
    const int vtid = tid & 127;
    const int half = tid >> 7;
    const int lx = vtid >> 5;          // 0..3
    const int ly = (vtid >> 3) & 3;    // 0..3
    const int lz = vtid & 7;           // 0..7
    const int v = ((tx + lx) * 100 + (ty + ly)) * 8 + lz;

    const float px = vox_coords[v * 3 + 0];
    const float py = vox_coords[v * 3 + 1];
    const float pz = vox_coords[v * 3 + 2];
    unsigned long long ppx, ppy, ppz;
    PACK2(ppx, px, px);
    PACK2(ppy, py, py);
    PACK2(ppz, pz, pz);

    const float dxy = 80.0f / 99.0f;
    const float bx0 = -40.0f + tx * dxy - CULL_MARGIN;
    const float bx1 = -40.0f + (tx + 3) * dxy + CULL_MARGIN;
    const float by0 = -40.0f + ty * dxy - CULL_MARGIN;
    const float by1 = -40.0f + (ty + 3) * dxy + CULL_MARGIN;
    const float bz0 = -1.0f - CULL_MARGIN;
    const float bz1 = 5.4f + CULL_MARGIN;

    __shared__ unsigned short s_list[N_GAUSS];          // 4 KB
    __shared__ float4 s_stage[(STAGE_CAP / 2) * 13];    // 26.6 KB; reused out
    __shared__ int s_warp_sums[8];

    // --- Phase 1: AABB cull on packed means (32 KB contiguous) ---
    const int gbase = tid * 8;
    unsigned int hitmask = 0;
#pragma unroll
    for (int i = 0; i < 8; i++) {
        const float4 p0 = __ldg(g_means + gbase + i);
        float ex = fmaxf(fmaxf(bx0 - p0.x, p0.x - bx1), 0.0f);
        float ey = fmaxf(fmaxf(by0 - p0.y, p0.y - by1), 0.0f);
        float ez = fmaxf(fmaxf(bz0 - p0.z, p0.z - bz1), 0.0f);
        if (ex * ex + ey * ey + ez * ez < RADIUS_SQ) hitmask |= (1u << i);
    }
    int cnt = __popc(hitmask);

    // Deterministic order-preserving compaction
    const int lane = tid & 31, wid = tid >> 5;
    int incl = cnt;
#pragma unroll
    for (int o = 1; o < 32; o <<= 1) {
        int vsh = __shfl_up_sync(0xffffffffu, incl, o);
        if (lane >= o) incl += vsh;
    }
    if (lane == 31) s_warp_sums[wid] = incl;
    __syncthreads();
    int woff = 0, total = 0;
#pragma unroll
    for (int w = 0; w < 8; w++) {
        int ws = s_warp_sums[w];
        if (w < wid) woff += ws;
        total += ws;
    }
    int offset = woff + incl - cnt;
    unsigned int m = hitmask;
    while (m) {
        int i = __ffs(m) - 1;
        m &= m - 1;
        s_list[offset++] = (unsigned short)(gbase + i);
    }
    __syncthreads();

    // --- Phase 2/3 chunked: stage pairs, packed accumulate ---
    unsigned long long accp[8];
#pragma unroll
    for (int i = 0; i < 8; i++) accp[i] = 0ull;   // == (0.0f, 0.0f)
    unsigned long long acc16p = 0ull;

    for (int base = 0; base < total; base += STAGE_CAP) {
        const int nc = min(STAGE_CAP, total - base);
        const int npairs = (nc + 1) >> 1;

        // Stage interleaved pair records: 13 float4s per pair.
        // f4[0]=(−mxa,−mxb,−mya,−myb) f4[1]=(−mza,−mzb,h00a,h00b)
        // f4[2]=(h01a,h01b,h02a,h02b) f4[3]=(h11a,h11b,h12a,h12b)
        // f4[4]=(h22a,h22b,s16a,s16b) f4[5..8]=a classes 0..15 pairs
        // f4[9..12]=b classes (zeroed if pad).
        for (int t = tid; t < npairs * 13; t += 256) {
            const int p = t / 13, j = t - p * 13;
            const int ia = (int)s_list[base + 2 * p];
            const bool bvalid = (2 * p + 1) < nc;
            const int ib = bvalid ? (int)s_list[base + 2 * p + 1] : ia;
            const float* fa = (const float*)(g_prep + ia * 7);
            const float* fb = (const float*)(g_prep + ib * 7);
            float4 ov;
            if (j < 5) {
                float a0 = __ldg(fa + 2 * j);
                float b0 = __ldg(fb + 2 * j);
                float a1 = __ldg(fa + 2 * j + 1);
                float b1 = __ldg(fb + 2 * j + 1);
                if (j == 4 && !bvalid) b1 = 0.0f;   // s16b = 0 for pad
                ov = make_float4(a0, b0, a1, b1);
            } else if (j < 9) {
                ov = __ldg((const float4*)fa + 3 + (j - 5));
            } else if (bvalid) {
                ov = __ldg((const float4*)fb + 3 + (j - 9));
            } else {
                ov = make_float4(0.0f, 0.0f, 0.0f, 0.0f);
            }
            s_stage[p * 13 + j] = ov;
        }
        __syncthreads();

        const int mid = npairs >> 1;
        const int p0i = half ? mid : 0;
        const int p1i = half ? npairs : mid;

        const ulonglong2* Q = (const ulonglong2*)(s_stage + p0i * 13);
#pragma unroll 2
        for (int p = p0i; p < p1i; p++, Q += 13) {
            const ulonglong2 q0 = Q[0];   // (-mx), (-my)
            const ulonglong2 q1 = Q[1];   // (-mz), (h00)
            const ulonglong2 q2 = Q[2];   // (h01), (h02)
            const ulonglong2 q3 = Q[3];   // (h11), (h12)
            const ulonglong2 q4 = Q[4];   // (h22), (s16)

            unsigned long long d0, d1, d2;
            ADD2(d0, ppx, q0.x);
            ADD2(d1, ppy, q0.y);
            ADD2(d2, ppz, q1.x);

            unsigned long long ds;
            MUL2(ds, d0, d0);
            FMA2(ds, d1, d1);
            FMA2(ds, d2, d2);

            unsigned long long t0, t1, u, em;
            MUL2(t0, q1.y, d0);
            FMA2(t0, q2.x, d1);
            FMA2(t0, q2.y, d2);
            MUL2(t1, q3.x, d1);
            FMA2(t1, q3.y, d2);
            MUL2(em, t0, d0);
            FMA2(em, t1, d1);
            MUL2(u, q4.x, d2);
            FMA2(em, u, d2);

            float dsa, dsb, ea, eb;
            UNPACK2(dsa, dsb, ds);
            UNPACK2(ea, eb, em);
            float wa, wb;
            EX2(wa, ea);
            EX2(wb, eb);
            wa = (dsa < RADIUS_SQ) ? wa : 0.0f;
            wb = (dsb < RADIUS_SQ) ? wb : 0.0f;
            unsigned long long wwa, wwb, wab;
            PACK2(wwa, wa, wa);
            PACK2(wwb, wb, wb);
            PACK2(wab, wa, wb);

            FMA2(acc16p, q4.y, wab);
            {
                const ulonglong2 qa = Q[5];
                FMA2(accp[0], qa.x, wwa); FMA2(accp[1], qa.y, wwa);
            }
            {
                const ulonglong2 qa = Q[6];
                FMA2(accp[2], qa.x, wwa); FMA2(accp[3], qa.y, wwa);
            }
            {
                const ulonglong2 qa = Q[7];
                FMA2(accp[4], qa.x, wwa); FMA2(accp[5], qa.y, wwa);
            }
            {
                const ulonglong2 qa = Q[8];
                FMA2(accp[6], qa.x, wwa); FMA2(accp[7], qa.y, wwa);
            }
            {
                const ulonglong2 qb = Q[9];
                FMA2(accp[0], qb.x, wwb); FMA2(accp[1], qb.y, wwb);
            }
            {
                const ulonglong2 qb = Q[10];
                FMA2(accp[2], qb.x, wwb); FMA2(accp[3], qb.y, wwb);
            }
            {
                const ulonglong2 qb = Q[11];
                FMA2(accp[4], qb.x, wwb); FMA2(accp[5], qb.y, wwb);
            }
            {
                const ulonglong2 qb = Q[12];
                FMA2(accp[6], qb.x, wwb); FMA2(accp[7], qb.y, wwb);
            }
        }
        __syncthreads();   // before next chunk overwrites s_stage
    }

    // Unpack accumulators: classes 0..15 from pairs, s16 = lo + hi.
    float acc[NUM_CLASSES];
#pragma unroll
    for (int i = 0; i < 8; i++) UNPACK2(acc[2 * i], acc[2 * i + 1], accp[i]);
    {
        float a16lo, a16hi;
        UNPACK2(a16lo, a16hi, acc16p);
        acc[16] = a16lo + a16hi;
    }

    // --- Combine halves + coalesced output via smem transpose ---
    float* s_out = (float*)s_stage;
    float* s_part = s_out + 128 * NUM_CLASSES;

    if (half) {
#pragma unroll
        for (int c = 0; c < NUM_CLASSES; c++)
            s_part[vtid * NUM_CLASSES + c] = acc[c];
    }
    __syncthreads();
    if (!half) {
#pragma unroll
        for (int c = 0; c < NUM_CLASSES; c++)
            acc[c] += s_part[vtid * NUM_CLASSES + c];

        // Empty term: center=(0,0,2.2), inv=(1/1600,1/1600,1/10.24)
        const float de2 = pz - 2.2f;
        const float me = px * px * (1.0f / 1600.0f)
                       + py * py * (1.0f / 1600.0f)
                       + de2 * de2 * (1.0f / 10.24f);
        acc[0] += 0.1f * __expf(-0.5f * me) * 5.0f;

#pragma unroll
        for (int c = 0; c < NUM_CLASSES; c++)
            s_out[vtid * NUM_CLASSES + c] = acc[c];
    }
    __syncthreads();

    // Cooperative coalesced store: for fixed lx, 544 contiguous gmem floats.
    {
        const float4* s4 = (const float4*)s_out;
        for (int t4 = tid; t4 < 544; t4 += 256) {
            const int lxb = t4 / 136;
            const int j4 = t4 - lxb * 136;
            float4* dst = (float4*)(out + ((size_t)((tx + lxb) * 100 + ty) * 8) * NUM_CLASSES);
            dst[j4] = s4[lxb * 136 + j4];
        }
    }
}

extern "C" void kernel_launch(void* const* d_in, const int* in_sizes, int n_in,
                              void* d_out, int out_size) {
    const float* props = (const float*)d_in[0];
    const float* vox   = (const float*)d_in[1];
    if (n_in >= 2 && in_sizes[0] == 100 * 100 * 8 * 3 &&
        in_sizes[1] == N_GAUSS * PROP_STRIDE) {
        const float* t = props; props = vox; vox = t;
    }
    float* out = (float*)d_out;

    prep_kernel<<<64, 32>>>(props);
    splat_kernel<<<dim3(25, 25), 256>>>(vox, out);
}